// round 16
// baseline (speedup 1.0000x reference)
#include <cuda_runtime.h>
#include <cuda_bf16.h>
#include <cuda_fp16.h>
#include <math.h>
#include <cstdint>

#define NN 50000
#define NE 800000
#define NT 850000          // NE + NN self loops
#define HID 128
#define EPSV 1e-5f

// ================= scratch (device globals; no allocations) =================
__device__ __align__(16) float g_x [NN*HID];
__device__ __align__(16) float g_xr[NN*HID];
__device__ __align__(16) float g_h [NN*HID];
__device__ __align__(16) __half g_xlh[NN*HID];   // xl fp16 gather table
__device__ __align__(16) __half g_ahi[NN*HID];   // x split hi (fp16) - layer0 feed
__device__ __align__(16) __half g_alo[NN*HID];   // x split lo (fp16)
// weights fp16: 4 layers x [k=128][n=256] ([Wl|Wr]) + skip [k=128][n=128]
__device__ __align__(16) __half g_wh[4*32768 + 16384];
__device__ int   g_cnt[NN];     // zero at load; re-zeroed by k_fused<false> each call
__device__ int   g_rowptr[NN+1];
__device__ int   g_fill[NN];
__device__ int   g_csrc[NT];
__device__ int   g_bsum[256];
__device__ int   g_bpre[256];
__device__ float g_stats[256];
__device__ float g_scale[HID];
__device__ float g_shift[HID];
__device__ int   g_ctr;

// ================= mma.sync helpers =================
__device__ __forceinline__ uint32_t smem_u32(const void* p){
  uint32_t a;
  asm("{ .reg .u64 t; cvta.to.shared.u64 t, %1; cvt.u32.u64 %0, t; }" : "=r"(a) : "l"(p));
  return a;
}
__device__ __forceinline__ void ldm4(uint32_t* r, uint32_t a){
  asm volatile("ldmatrix.sync.aligned.m8n8.x4.shared.b16 {%0,%1,%2,%3}, [%4];"
    : "=r"(r[0]),"=r"(r[1]),"=r"(r[2]),"=r"(r[3]) : "r"(a));
}
__device__ __forceinline__ void ldm4t(uint32_t* r, uint32_t a){
  asm volatile("ldmatrix.sync.aligned.m8n8.x4.trans.shared.b16 {%0,%1,%2,%3}, [%4];"
    : "=r"(r[0]),"=r"(r[1]),"=r"(r[2]),"=r"(r[3]) : "r"(a));
}
__device__ __forceinline__ void mma_f16(float* c, const uint32_t* a, const uint32_t* b){
  asm volatile("mma.sync.aligned.m16n8k16.row.col.f32.f16.f16.f32 "
    "{%0,%1,%2,%3}, {%4,%5,%6,%7}, {%8,%9}, {%0,%1,%2,%3};"
    : "+f"(c[0]),"+f"(c[1]),"+f"(c[2]),"+f"(c[3])
    : "r"(a[0]),"r"(a[1]),"r"(a[2]),"r"(a[3]), "r"(b[0]),"r"(b[1]));
}
__device__ __forceinline__ uint32_t swA(int r, int c2){   // A tile: 64 rows x 256B
  int u = c2 >> 4;
  u = (u & 8) | ((u ^ (r & 7)) & 7);
  return (uint32_t)(r*256 + (u << 4) + (c2 & 15));
}
__device__ __forceinline__ uint32_t swB128(int r, int c2){ // B tile: 128 rows x 256B
  int u = c2 >> 4;
  u = (u & ~7) | ((u ^ (r & 7)) & 7);
  return (uint32_t)(r*256 + (u << 4) + (c2 & 15));
}

#define SM_ALO 16384
#define SM_B   32768
#define SMEM_TOT 65536      // 64 KB -> 3 CTAs/SM

// 2-term 128-col compute over M=64, 8 warps: D = Ahi@B + Alo@B.
__device__ __forceinline__ void mma_compute64(uint32_t sb, float acc[2][4][4], int wid, int lane){
  const int warp_m = wid >> 2, warp_n = wid & 3;   // warp_m 0..1, warp_n 0..3
  const int arow = warp_m*32 + (lane & 15);
  const int ac2b = (lane >> 4) << 4;
  const int bgrp = lane >> 3;
  const int bkr  = ((bgrp & 1) << 3) + (lane & 7);
  const int bnc  = warp_n*32 + ((bgrp >> 1) << 3);

  #pragma unroll
  for(int ks = 0; ks < 8; ks++){
    uint32_t bf[4][2], tmp[4];
    #pragma unroll
    for(int np = 0; np < 2; np++){
      uint32_t boff = swB128(ks*16 + bkr, (bnc + np*16)*2);
      ldm4t(tmp, sb + SM_B + boff);
      bf[np*2][0]=tmp[0]; bf[np*2][1]=tmp[1]; bf[np*2+1][0]=tmp[2]; bf[np*2+1][1]=tmp[3];
    }
    uint32_t a[2][4];
    #pragma unroll
    for(int mt = 0; mt < 2; mt++)
      ldm4(a[mt], sb + swA(arow + mt*16, ks*32 + ac2b));
    #pragma unroll
    for(int mt = 0; mt < 2; mt++)
      #pragma unroll
      for(int nt = 0; nt < 4; nt++)
        mma_f16(acc[mt][nt], a[mt], bf[nt]);
    #pragma unroll
    for(int mt = 0; mt < 2; mt++)
      ldm4(a[mt], sb + SM_ALO + swA(arow + mt*16, ks*32 + ac2b));
    #pragma unroll
    for(int mt = 0; mt < 2; mt++)
      #pragma unroll
      for(int nt = 0; nt < 4; nt++)
        mma_f16(acc[mt][nt], a[mt], bf[nt]);
  }
}

__device__ __forceinline__ void fill_B128(char* smem, int tid,
  const __half* __restrict__ Wg, int stride, int col_off){
  for(int ch = tid; ch < 2048; ch += 256){
    int r = ch >> 4, c2 = (ch & 15) * 16;
    uint32_t off = swB128(r, c2);
    *(uint4*)(smem + SM_B + off) = *(const uint4*)(Wg + r*stride + col_off + (c2 >> 1));
  }
}

// epilogue for a 128-col pass over 64 rows: OUT=0 -> g_xlh (fp16), OUT=1 -> g_xr (fp32)
template<int OUT>
__device__ __forceinline__ void ep64(float acc[2][4][4], int bm, int wid, int lane){
  const int warp_m = wid >> 2, warp_n = wid & 3;
  #pragma unroll
  for(int mt = 0; mt < 2; mt++){
    int r0 = bm + warp_m*32 + mt*16 + (lane >> 2);
    #pragma unroll
    for(int nt = 0; nt < 4; nt++){
      int col = warp_n*32 + nt*8 + (lane & 3)*2;
      #pragma unroll
      for(int half = 0; half < 2; half++){
        int grow = r0 + half*8;
        if(grow >= NN) continue;
        float v0 = acc[mt][nt][half*2], v1 = acc[mt][nt][half*2+1];
        if(OUT == 0)
          *(__half2*)(g_xlh + grow*128 + col) = __floats2half2_rn(v0, v1);
        else
          *(float2*)(g_xr + grow*128 + col) = make_float2(v0, v1);
      }
    }
  }
}

#define ZERO_ACC(acc) { _Pragma("unroll") for(int mt=0;mt<2;mt++) _Pragma("unroll") for(int nt=0;nt<4;nt++) _Pragma("unroll") for(int r=0;r<4;r++) acc[mt][nt][r]=0.f; }

// ================= setup: weights->fp16 + x copy/split + edge count =================
__global__ void k_setup(const float* __restrict__ x, const int* __restrict__ ei,
                        const float* __restrict__ Wl, const float* __restrict__ Wr,
                        const float* __restrict__ skW){
  int i = blockIdx.x*blockDim.x + threadIdx.x;
  if(i < 4*32768 + 16384){
    float v;
    if(i < 4*32768){
      int l = i >> 15, rem = i & 32767, k = rem >> 8, n = rem & 255;
      v = (n < 128) ? Wl[l*16384 + k*128 + n] : Wr[l*16384 + k*128 + (n-128)];
    } else {
      v = skW[i - 4*32768];
    }
    g_wh[i] = __float2half_rn(v);
  }
  if(i < NT){
    int d = (i < NE) ? ei[NE + i] : (i - NE);
    atomicAdd(&g_cnt[d], 1);
  }
  if(i >= NN*32) return;
  float4 v = ((const float4*)x)[i];
  ((float4*)g_x)[i] = v;
  __half2 h0, h1, l0, l1;
  h0.x = __float2half_rn(v.x); h0.y = __float2half_rn(v.y);
  h1.x = __float2half_rn(v.z); h1.y = __float2half_rn(v.w);
  l0.x = __float2half_rn(v.x - __half2float(h0.x));
  l0.y = __float2half_rn(v.y - __half2float(h0.y));
  l1.x = __float2half_rn(v.z - __half2float(h1.x));
  l1.y = __float2half_rn(v.w - __half2float(h1.y));
  ((__half2*)g_ahi)[2*i] = h0; ((__half2*)g_ahi)[2*i+1] = h1;
  ((__half2*)g_alo)[2*i] = l0; ((__half2*)g_alo)[2*i+1] = l1;
}
#define SCAN_B 196
__global__ void k_blocksum(){
  __shared__ int sh[256];
  __shared__ int s_last;
  int t = threadIdx.x;
  int i = blockIdx.x*256 + t;
  sh[t] = (i < NN) ? g_cnt[i] : 0; __syncthreads();
  #pragma unroll
  for(int off = 128; off > 0; off >>= 1){
    if(t < off) sh[t] += sh[t+off];
    __syncthreads();
  }
  if(t == 0) g_bsum[blockIdx.x] = sh[0];
  __threadfence();
  if(t == 0){
    int v = atomicAdd(&g_ctr, 1);
    s_last = (v == (int)gridDim.x - 1);
  }
  __syncthreads();
  if(s_last){
    int v = (t < SCAN_B) ? g_bsum[t] : 0;
    sh[t] = v; __syncthreads();
    #pragma unroll
    for(int off = 1; off < 256; off <<= 1){
      int u = (t >= off) ? sh[t-off] : 0;
      __syncthreads(); sh[t] += u; __syncthreads();
    }
    if(t < SCAN_B) g_bpre[t] = sh[t] - v;
    if(t == 255) g_rowptr[NN] = sh[255];
    if(t == 0) g_ctr = 0;
  }
}
__global__ void k_rowptr(){
  __shared__ int sh[256];
  int t = threadIdx.x;
  int i = blockIdx.x*256 + t;
  int v = (i < NN) ? g_cnt[i] : 0;
  sh[t] = v; __syncthreads();
  #pragma unroll
  for(int off = 1; off < 256; off <<= 1){
    int u = (t >= off) ? sh[t-off] : 0;
    __syncthreads(); sh[t] += u; __syncthreads();
  }
  if(i < NN){
    int e = sh[t] - v + g_bpre[blockIdx.x];
    g_rowptr[i] = e; g_fill[i] = e;
  }
}
__global__ void k_scatter(const int* __restrict__ ei){
  int base = (blockIdx.x*blockDim.x + threadIdx.x)*4;
  int s[4], d[4], pos[4];
  bool val[4];
  #pragma unroll
  for(int j = 0; j < 4; j++){
    int e = base + j;
    val[j] = e < NT;
    if(val[j]){
      if(e < NE){ s[j] = ei[e]; d[j] = ei[NE + e]; }
      else      { s[j] = d[j] = e - NE; }
    }
  }
  #pragma unroll
  for(int j = 0; j < 4; j++)
    if(val[j]) pos[j] = atomicAdd(&g_fill[d[j]], 1);
  #pragma unroll
  for(int j = 0; j < 4; j++)
    if(val[j]) g_csrc[pos[j]] = s[j];
}

// ================= layer-0 LR GEMM (two 128-col passes, M=64 tiles) =================
__global__ void __launch_bounds__(256, 3) k_mma_lr0(){
  extern __shared__ __align__(16) char smem[];
  const int tid = threadIdx.x, wid = tid >> 5, lane = tid & 31;
  const int bm = blockIdx.x * 64;
  const uint32_t sb = smem_u32(smem);
  for(int ch = tid; ch < 1024; ch += 256){
    int r = ch >> 4, c2 = (ch & 15) << 4;
    int grow = bm + r;
    uint32_t off = swA(r, c2);
    uint4 vh = make_uint4(0,0,0,0), vl = vh;
    if(grow < NN){
      vh = *(const uint4*)(g_ahi + grow*128 + (c2 >> 1));
      vl = *(const uint4*)(g_alo + grow*128 + (c2 >> 1));
    }
    *(uint4*)(smem + off)          = vh;
    *(uint4*)(smem + SM_ALO + off) = vl;
  }
  fill_B128(smem, tid, g_wh, 256, 0);         // Wl half
  __syncthreads();
  float acc[2][4][4];
  ZERO_ACC(acc);
  mma_compute64(sb, acc, wid, lane);
  __syncthreads();                            // B reads complete
  ep64<0>(acc, bm, wid, lane);                // overlap: epilogue stores ...
  fill_B128(smem, tid, g_wh, 256, 128);       // ... with Wr-half B fill
  __syncthreads();
  ZERO_ACC(acc);
  mma_compute64(sb, acc, wid, lane);
  ep64<1>(acc, bm, wid, lane);
}

// ================= fused skip-GEMM (+ next-layer LR GEMM, or final FC) =================
template<bool DO_LR>
__global__ void __launch_bounds__(256, 3) k_fused(const float* __restrict__ bias, int next_layer,
                                                  const float* __restrict__ fw,
                                                  const float* __restrict__ fb,
                                                  float* __restrict__ out){
  extern __shared__ __align__(16) char smem[];
  const int tid = threadIdx.x, wid = tid >> 5, lane = tid & 31;
  const int bm = blockIdx.x * 64;
  const uint32_t sb = smem_u32(smem);

  // ---- prologue: A = fp16split(normelu(h)), B = skW ----
  for(int ch = tid; ch < 1024; ch += 256){
    int r = ch >> 4, c2 = (ch & 15) << 4;
    int grow = bm + r;
    uint32_t off = swA(r, c2);
    int c = c2 >> 1;
    __half2 hh[4], ll[4];
    if(grow < NN){
      #pragma unroll
      for(int q = 0; q < 2; q++){
        float4 v  = *(const float4*)(g_h + grow*128 + c + q*4);
        float4 sc = *(const float4*)(g_scale + c + q*4);
        float4 sh = *(const float4*)(g_shift + c + q*4);
        float z0 = fmaf(v.x, sc.x, sh.x); z0 = z0 > 0.f ? z0 : (__expf(z0) - 1.f);
        float z1 = fmaf(v.y, sc.y, sh.y); z1 = z1 > 0.f ? z1 : (__expf(z1) - 1.f);
        float z2 = fmaf(v.z, sc.z, sh.z); z2 = z2 > 0.f ? z2 : (__expf(z2) - 1.f);
        float z3 = fmaf(v.w, sc.w, sh.w); z3 = z3 > 0.f ? z3 : (__expf(z3) - 1.f);
        hh[q*2].x   = __float2half_rn(z0); hh[q*2].y   = __float2half_rn(z1);
        hh[q*2+1].x = __float2half_rn(z2); hh[q*2+1].y = __float2half_rn(z3);
        ll[q*2].x   = __float2half_rn(z0 - __half2float(hh[q*2].x));
        ll[q*2].y   = __float2half_rn(z1 - __half2float(hh[q*2].y));
        ll[q*2+1].x = __float2half_rn(z2 - __half2float(hh[q*2+1].x));
        ll[q*2+1].y = __float2half_rn(z3 - __half2float(hh[q*2+1].y));
      }
    } else {
      #pragma unroll
      for(int q = 0; q < 4; q++){ hh[q].x = hh[q].y = __float2half_rn(0.f); ll[q] = hh[q]; }
    }
    *(uint4*)(smem + off)          = *(uint4*)hh;
    *(uint4*)(smem + SM_ALO + off) = *(uint4*)ll;
  }
  fill_B128(smem, tid, g_wh + 4*32768, 128, 0);
  __syncthreads();

  // ---- skip GEMM ----
  {
    float acc[2][4][4];
    ZERO_ACC(acc);
    mma_compute64(sb, acc, wid, lane);
    __syncthreads();               // A/B reads complete

    // ---- epilogue: x update + new A splits into SMEM, overlapped with Wl B fill ----
    const int warp_m = wid >> 2, warp_n = wid & 3;
    #pragma unroll
    for(int mt = 0; mt < 2; mt++){
      int rloc0 = warp_m*32 + mt*16 + (lane >> 2);
      #pragma unroll
      for(int nt = 0; nt < 4; nt++){
        int col = warp_n*32 + nt*8 + (lane & 3)*2;
        #pragma unroll
        for(int half = 0; half < 2; half++){
          int rloc = rloc0 + half*8;
          int grow = bm + rloc;
          float v0 = acc[mt][nt][half*2], v1 = acc[mt][nt][half*2+1];
          if(grow < NN){
            float2 old = *(const float2*)(g_x + grow*128 + col);
            v0 += bias[col]   + old.x;
            v1 += bias[col+1] + old.y;
            *(float2*)(g_x + grow*128 + col) = make_float2(v0, v1);
          } else { v0 = 0.f; v1 = 0.f; }
          if(DO_LR){
            __half2 h, l;
            h.x = __float2half_rn(v0); h.y = __float2half_rn(v1);
            l.x = __float2half_rn(v0 - __half2float(h.x));
            l.y = __float2half_rn(v1 - __half2float(h.y));
            uint32_t off = swA(rloc, col*2);
            *(__half2*)(smem + off)          = h;
            *(__half2*)(smem + SM_ALO + off) = l;
          }
        }
      }
    }
    if(DO_LR)
      fill_B128(smem, tid, g_wh + next_layer*32768, 256, 0);  // Wl half, overlapped
  }
  if(!DO_LR){
    // ---- fused final FC + g_cnt re-zero for next call ----
    __syncthreads();
    int row = bm + (tid >> 2);
    int part = tid & 3;
    int rowc = row < NN ? row : (NN - 1);
    const float4* xp = (const float4*)(g_x + rowc*128 + part*32);
    float s = 0.f;
    #pragma unroll
    for(int q = 0; q < 8; q++){
      float4 v = xp[q];
      float4 w = *(const float4*)(fw + part*32 + q*4);
      s += v.x*w.x + v.y*w.y + v.z*w.z + v.w*w.w;
    }
    s += __shfl_xor_sync(0xffffffffu, s, 1);
    s += __shfl_xor_sync(0xffffffffu, s, 2);
    if(part == 0 && row < NN) out[row] = s + fb[0];
    for(int i = blockIdx.x*256 + tid; i < NN; i += gridDim.x*256)
      g_cnt[i] = 0;
    return;
  }

  __syncthreads();                 // A rewrite + B(Wl) fill visible
  {
    float acc[2][4][4];
    ZERO_ACC(acc);
    mma_compute64(sb, acc, wid, lane);
    __syncthreads();               // B reads complete
    ep64<0>(acc, bm, wid, lane);   // overlap epilogue with Wr B fill
    fill_B128(smem, tid, g_wh + next_layer*32768, 256, 128);
  }
  __syncthreads();
  {
    float acc[2][4][4];
    ZERO_ACC(acc);
    mma_compute64(sb, acc, wid, lane);
    ep64<1>(acc, bm, wid, lane);
  }
}

// ================= GATv2 (proven round-10 form) + fused GraphNorm =================
__device__ __forceinline__ float lrelu(float v){ return v > 0.f ? v : 0.2f*v; }

__global__ void __launch_bounds__(256) k_gat(const float* __restrict__ att,
                                             const float* __restrict__ convb,
                                             const float* __restrict__ gnw,
                                             const float* __restrict__ gnb,
                                             const float* __restrict__ gnms){
  __shared__ float s_sum[8][128];
  __shared__ float s_sq [8][128];
  __shared__ int s_last;
  int tid = threadIdx.x, wid = tid >> 5, lane = tid & 31;
  int node = blockIdx.x*8 + wid;
  int c4 = lane * 4;
  float4 o = make_float4(0.f, 0.f, 0.f, 0.f);

  if(node < NN){
    const float4 xr4 = *(const float4*)(g_xr + node*128 + c4);
    const float4 at4 = *(const float4*)(att + c4);
    int pb = g_rowptr[node], pe = g_rowptr[node+1];

    float m = -3.4e38f, ds = 0.f;
    float a0 = 0.f, a1 = 0.f, a2 = 0.f, a3 = 0.f;

    if(pb < pe){
      int sA = g_csrc[pb];
      uint2 rawN = *(const uint2*)(g_xlh + sA*128 + c4);
      int sB = (pb+1 < pe) ? g_csrc[pb+1] : 0;
      for(int p = pb; p < pe; p++){
        uint2 raw = rawN;
        if(p+1 < pe){
          rawN = *(const uint2*)(g_xlh + sB*128 + c4);
          if(p+2 < pe) sB = g_csrc[p+2];
        }
        float2 f0 = __half22float2(*(__half2*)&raw.x);
        float2 f1 = __half22float2(*(__half2*)&raw.y);
        float t = lrelu(f0.x + xr4.x)*at4.x + lrelu(f0.y + xr4.y)*at4.y
                + lrelu(f1.x + xr4.z)*at4.z + lrelu(f1.y + xr4.w)*at4.w;
        t += __shfl_xor_sync(0xffffffffu, t, 4);
        t += __shfl_xor_sync(0xffffffffu, t, 2);
        t += __shfl_xor_sync(0xffffffffu, t, 1);
        if(t <= m){
          float a = __expf(t - m);
          ds += a;
          a0 = fmaf(a, f0.x, a0); a1 = fmaf(a, f0.y, a1);
          a2 = fmaf(a, f1.x, a2); a3 = fmaf(a, f1.y, a3);
        } else {
          float f = __expf(m - t);
          ds = fmaf(ds, f, 1.f);
          a0 = fmaf(a0, f, f0.x); a1 = fmaf(a1, f, f0.y);
          a2 = fmaf(a2, f, f1.x); a3 = fmaf(a3, f, f1.y);
          m = t;
        }
      }
    }
    float inv = 1.f / ds;
    const float4 bb = *(const float4*)(convb + c4);
    o.x = fmaf(a0, inv, bb.x); o.y = fmaf(a1, inv, bb.y);
    o.z = fmaf(a2, inv, bb.z); o.w = fmaf(a3, inv, bb.w);
    *(float4*)(g_h + node*128 + c4) = o;
  }

  s_sum[wid][c4]   = o.x;     s_sum[wid][c4+1] = o.y;
  s_sum[wid][c4+2] = o.z;     s_sum[wid][c4+3] = o.w;
  s_sq [wid][c4]   = o.x*o.x; s_sq [wid][c4+1] = o.y*o.y;
  s_sq [wid][c4+2] = o.z*o.z; s_sq [wid][c4+3] = o.w*o.w;
  __syncthreads();
  if(tid < 128){
    float s = 0.f, q = 0.f;
    #pragma unroll
    for(int w = 0; w < 8; w++){ s += s_sum[w][tid]; q += s_sq[w][tid]; }
    atomicAdd(&g_stats[tid], s);
    atomicAdd(&g_stats[128 + tid], q);
  }
  __threadfence();
  if(tid == 0){
    int v = atomicAdd(&g_ctr, 1);
    s_last = (v == (int)gridDim.x - 1);
  }
  __syncthreads();
  if(s_last){
    if(tid < 128){
      float sum = g_stats[tid], sq = g_stats[128 + tid];
      float mean = sum * (1.f/(float)NN);
      float mv = gnms[tid] * mean;
      float var = sq * (1.f/(float)NN) - 2.f*mv*mean + mv*mv;
      float sc = gnw[tid] * rsqrtf(var + EPSV);
      g_scale[tid] = sc;
      g_shift[tid] = gnb[tid] - mv*sc;
      g_stats[tid] = 0.f; g_stats[128 + tid] = 0.f;
    }
    if(tid == 0) g_ctr = 0;
  }
}

// ================= launcher =================
extern "C" void kernel_launch(void* const* d_in, const int* in_sizes, int n_in,
                              void* d_out, int out_size){
  const float* x     = (const float*)d_in[0];
  const int*   ei    = (const int*)  d_in[1];
  const float* Wl    = (const float*)d_in[2];
  const float* Wr    = (const float*)d_in[3];
  const float* att   = (const float*)d_in[4];
  const float* convb = (const float*)d_in[5];
  const float* gnw   = (const float*)d_in[6];
  const float* gnb   = (const float*)d_in[7];
  const float* gnms  = (const float*)d_in[8];
  const float* skW   = (const float*)d_in[9];
  const float* skb   = (const float*)d_in[10];
  const float* fcW   = (const float*)d_in[11];
  const float* fcb   = (const float*)d_in[12];
  float* out = (float*)d_out;

  static int cfg_done = 0;
  static cudaStream_t s2;
  static cudaEvent_t evFork, evJoin;
  if(!cfg_done){
    cudaFuncSetAttribute(k_mma_lr0,      cudaFuncAttributeMaxDynamicSharedMemorySize, SMEM_TOT);
    cudaFuncSetAttribute(k_fused<true>,  cudaFuncAttributeMaxDynamicSharedMemorySize, SMEM_TOT);
    cudaFuncSetAttribute(k_fused<false>, cudaFuncAttributeMaxDynamicSharedMemorySize, SMEM_TOT);
    cudaStreamCreateWithFlags(&s2, cudaStreamNonBlocking);
    cudaEventCreateWithFlags(&evFork, cudaEventDisableTiming);
    cudaEventCreateWithFlags(&evJoin, cudaEventDisableTiming);
    cfg_done = 1;
  }

  k_setup<<<(NN*32 + 255)/256, 256>>>(x, ei, Wl, Wr, skW);
  // fork: CSR chain on s2, overlapping with layer-0 GEMM on the main stream
  cudaEventRecord(evFork, 0);
  cudaStreamWaitEvent(s2, evFork, 0);
  k_blocksum<<<SCAN_B, 256, 0, s2>>>();
  k_rowptr  <<<SCAN_B, 256, 0, s2>>>();
  k_scatter <<<(NT/4 + 255)/256, 256, 0, s2>>>(ei);
  cudaEventRecord(evJoin, s2);

  const int MMA_GRID = (NN + 63)/64;         // 782
  const int GAT_GRID = (NN + 7)/8;           // 6250
  k_mma_lr0<<<MMA_GRID, 256, SMEM_TOT>>>();
  cudaStreamWaitEvent(0, evJoin, 0);         // join before first gat
  for(int l = 0; l < 4; l++){
    k_gat<<<GAT_GRID, 256>>>(att + l*HID, convb + l*HID,
                             gnw + l*HID, gnb + l*HID, gnms + l*HID);
    if(l < 3) k_fused<true> <<<MMA_GRID, 256, SMEM_TOT>>>(skb, l + 1, nullptr, nullptr, nullptr);
    else      k_fused<false><<<MMA_GRID, 256, SMEM_TOT>>>(skb, 0, fcW, fcb, out);
  }
}

// round 17
// speedup vs baseline: 1.0116x; 1.0116x over previous
#include <cuda_runtime.h>
#include <cuda_bf16.h>
#include <cuda_fp16.h>
#include <math.h>
#include <cstdint>

#define NN 50000
#define NE 800000
#define NT 850000          // NE + NN self loops
#define HID 128
#define EPSV 1e-5f

// ================= scratch (device globals; no allocations) =================
__device__ __align__(16) float g_x [NN*HID];
__device__ __align__(16) float g_xr[NN*HID];
__device__ __align__(16) float g_h [NN*HID];
__device__ __align__(16) __half g_xlh[NN*HID];   // xl fp16 gather table
__device__ __align__(16) __half g_ahi[NN*HID];   // x split hi (fp16) - layer0 feed
__device__ __align__(16) __half g_alo[NN*HID];   // x split lo (fp16)
// weights fp16: 4 layers x [k=128][n=256] ([Wl|Wr]) + skip [k=128][n=128]
__device__ __align__(16) __half g_wh[4*32768 + 16384];
__device__ int   g_cnt[NN];     // zero at load; re-zeroed by k_fused<false> each call
__device__ int   g_rowptr[NN+1];
__device__ int   g_fill[NN];
__device__ int   g_csrc[NT];
__device__ int   g_bsum[256];
__device__ int   g_bpre[256];
__device__ float g_stats[256];
__device__ float g_scale[HID];
__device__ float g_shift[HID];
__device__ int   g_ctr;

// ================= mma.sync helpers =================
__device__ __forceinline__ uint32_t smem_u32(const void* p){
  uint32_t a;
  asm("{ .reg .u64 t; cvta.to.shared.u64 t, %1; cvt.u32.u64 %0, t; }" : "=r"(a) : "l"(p));
  return a;
}
__device__ __forceinline__ void ldm4(uint32_t* r, uint32_t a){
  asm volatile("ldmatrix.sync.aligned.m8n8.x4.shared.b16 {%0,%1,%2,%3}, [%4];"
    : "=r"(r[0]),"=r"(r[1]),"=r"(r[2]),"=r"(r[3]) : "r"(a));
}
__device__ __forceinline__ void ldm4t(uint32_t* r, uint32_t a){
  asm volatile("ldmatrix.sync.aligned.m8n8.x4.trans.shared.b16 {%0,%1,%2,%3}, [%4];"
    : "=r"(r[0]),"=r"(r[1]),"=r"(r[2]),"=r"(r[3]) : "r"(a));
}
__device__ __forceinline__ void mma_f16(float* c, const uint32_t* a, const uint32_t* b){
  asm volatile("mma.sync.aligned.m16n8k16.row.col.f32.f16.f16.f32 "
    "{%0,%1,%2,%3}, {%4,%5,%6,%7}, {%8,%9}, {%0,%1,%2,%3};"
    : "+f"(c[0]),"+f"(c[1]),"+f"(c[2]),"+f"(c[3])
    : "r"(a[0]),"r"(a[1]),"r"(a[2]),"r"(a[3]), "r"(b[0]),"r"(b[1]));
}
__device__ __forceinline__ uint32_t swA(int r, int c2){
  int u = c2 >> 4;
  u = (u & 8) | ((u ^ (r & 7)) & 7);
  return (uint32_t)(r*256 + (u << 4) + (c2 & 15));
}
__device__ __forceinline__ uint32_t swB128(int r, int c2){   // B tile: 128 rows x 256B
  int u = c2 >> 4;
  u = (u & ~7) | ((u ^ (r & 7)) & 7);
  return (uint32_t)(r*256 + (u << 4) + (c2 & 15));
}

#define SM_ALO 32768
#define SM_B   65536
#define SMEM_TOT 98304      // 96 KB -> 2 CTAs/SM

// 2-term 128-col compute: D = Ahi@B + Alo@B.
__device__ __forceinline__ void mma_compute128(uint32_t sb, float acc[2][4][4], int wid, int lane){
  const int warp_m = wid >> 2, warp_n = wid & 3;
  const int arow = warp_m*32 + (lane & 15);
  const int ac2b = (lane >> 4) << 4;
  const int bgrp = lane >> 3;
  const int bkr  = ((bgrp & 1) << 3) + (lane & 7);
  const int bnc  = warp_n*32 + ((bgrp >> 1) << 3);

  #pragma unroll
  for(int ks = 0; ks < 8; ks++){
    uint32_t bf[4][2], tmp[4];
    #pragma unroll
    for(int np = 0; np < 2; np++){
      uint32_t boff = swB128(ks*16 + bkr, (bnc + np*16)*2);
      ldm4t(tmp, sb + SM_B + boff);
      bf[np*2][0]=tmp[0]; bf[np*2][1]=tmp[1]; bf[np*2+1][0]=tmp[2]; bf[np*2+1][1]=tmp[3];
    }
    uint32_t a[2][4];
    #pragma unroll
    for(int mt = 0; mt < 2; mt++)
      ldm4(a[mt], sb + swA(arow + mt*16, ks*32 + ac2b));
    #pragma unroll
    for(int mt = 0; mt < 2; mt++)
      #pragma unroll
      for(int nt = 0; nt < 4; nt++)
        mma_f16(acc[mt][nt], a[mt], bf[nt]);
    #pragma unroll
    for(int mt = 0; mt < 2; mt++)
      ldm4(a[mt], sb + SM_ALO + swA(arow + mt*16, ks*32 + ac2b));
    #pragma unroll
    for(int mt = 0; mt < 2; mt++)
      #pragma unroll
      for(int nt = 0; nt < 4; nt++)
        mma_f16(acc[mt][nt], a[mt], bf[nt]);
  }
}

__device__ __forceinline__ void fill_B128(char* smem, int tid,
  const __half* __restrict__ Wg, int stride, int col_off){
  for(int ch = tid; ch < 2048; ch += 512){
    int r = ch >> 4, c2 = (ch & 15) * 16;
    uint32_t off = swB128(r, c2);
    *(uint4*)(smem + SM_B + off) = *(const uint4*)(Wg + r*stride + col_off + (c2 >> 1));
  }
}

// epilogue for a 128-col pass: OUT=0 -> g_xlh (fp16), OUT=1 -> g_xr (fp32)
template<int OUT>
__device__ __forceinline__ void ep128(float acc[2][4][4], int bm, int wid, int lane){
  const int warp_m = wid >> 2, warp_n = wid & 3;
  #pragma unroll
  for(int mt = 0; mt < 2; mt++){
    int r0 = bm + warp_m*32 + mt*16 + (lane >> 2);
    #pragma unroll
    for(int nt = 0; nt < 4; nt++){
      int col = warp_n*32 + nt*8 + (lane & 3)*2;
      #pragma unroll
      for(int half = 0; half < 2; half++){
        int grow = r0 + half*8;
        if(grow >= NN) continue;
        float v0 = acc[mt][nt][half*2], v1 = acc[mt][nt][half*2+1];
        if(OUT == 0)
          *(__half2*)(g_xlh + grow*128 + col) = __floats2half2_rn(v0, v1);
        else
          *(float2*)(g_xr + grow*128 + col) = make_float2(v0, v1);
      }
    }
  }
}

#define ZERO_ACC(acc) { _Pragma("unroll") for(int mt=0;mt<2;mt++) _Pragma("unroll") for(int nt=0;nt<4;nt++) _Pragma("unroll") for(int r=0;r<4;r++) acc[mt][nt][r]=0.f; }

// ================= setup: weights->fp16 + x copy/split + edge count =================
__global__ void k_setup(const float* __restrict__ x, const int* __restrict__ ei,
                        const float* __restrict__ Wl, const float* __restrict__ Wr,
                        const float* __restrict__ skW){
  int i = blockIdx.x*blockDim.x + threadIdx.x;
  if(i < 4*32768 + 16384){
    float v;
    if(i < 4*32768){
      int l = i >> 15, rem = i & 32767, k = rem >> 8, n = rem & 255;
      v = (n < 128) ? Wl[l*16384 + k*128 + n] : Wr[l*16384 + k*128 + (n-128)];
    } else {
      v = skW[i - 4*32768];
    }
    g_wh[i] = __float2half_rn(v);
  }
  if(i < NT){
    int d = (i < NE) ? ei[NE + i] : (i - NE);
    atomicAdd(&g_cnt[d], 1);
  }
  if(i >= NN*32) return;
  float4 v = ((const float4*)x)[i];
  ((float4*)g_x)[i] = v;
  __half2 h0, h1, l0, l1;
  h0.x = __float2half_rn(v.x); h0.y = __float2half_rn(v.y);
  h1.x = __float2half_rn(v.z); h1.y = __float2half_rn(v.w);
  l0.x = __float2half_rn(v.x - __half2float(h0.x));
  l0.y = __float2half_rn(v.y - __half2float(h0.y));
  l1.x = __float2half_rn(v.z - __half2float(h1.x));
  l1.y = __float2half_rn(v.w - __half2float(h1.y));
  ((__half2*)g_ahi)[2*i] = h0; ((__half2*)g_ahi)[2*i+1] = h1;
  ((__half2*)g_alo)[2*i] = l0; ((__half2*)g_alo)[2*i+1] = l1;
}
#define SCAN_B 196
__global__ void k_blocksum(){
  __shared__ int sh[256];
  __shared__ int s_last;
  int t = threadIdx.x;
  int i = blockIdx.x*256 + t;
  sh[t] = (i < NN) ? g_cnt[i] : 0; __syncthreads();
  #pragma unroll
  for(int off = 128; off > 0; off >>= 1){
    if(t < off) sh[t] += sh[t+off];
    __syncthreads();
  }
  if(t == 0) g_bsum[blockIdx.x] = sh[0];
  __threadfence();
  if(t == 0){
    int v = atomicAdd(&g_ctr, 1);
    s_last = (v == (int)gridDim.x - 1);
  }
  __syncthreads();
  if(s_last){
    int v = (t < SCAN_B) ? g_bsum[t] : 0;
    sh[t] = v; __syncthreads();
    #pragma unroll
    for(int off = 1; off < 256; off <<= 1){
      int u = (t >= off) ? sh[t-off] : 0;
      __syncthreads(); sh[t] += u; __syncthreads();
    }
    if(t < SCAN_B) g_bpre[t] = sh[t] - v;
    if(t == 255) g_rowptr[NN] = sh[255];
    if(t == 0) g_ctr = 0;
  }
}
__global__ void k_rowptr(){
  __shared__ int sh[256];
  int t = threadIdx.x;
  int i = blockIdx.x*256 + t;
  int v = (i < NN) ? g_cnt[i] : 0;
  sh[t] = v; __syncthreads();
  #pragma unroll
  for(int off = 1; off < 256; off <<= 1){
    int u = (t >= off) ? sh[t-off] : 0;
    __syncthreads(); sh[t] += u; __syncthreads();
  }
  if(i < NN){
    int e = sh[t] - v + g_bpre[blockIdx.x];
    g_rowptr[i] = e; g_fill[i] = e;
  }
}
// batched scatter: 8 edges/thread, independent atomics for deep MLP
__global__ void k_scatter(const int* __restrict__ ei){
  int base = (blockIdx.x*blockDim.x + threadIdx.x)*8;
  int s[8], d[8], pos[8];
  bool val[8];
  #pragma unroll
  for(int j = 0; j < 8; j++){
    int e = base + j;
    val[j] = e < NT;
    if(val[j]){
      if(e < NE){ s[j] = ei[e]; d[j] = ei[NE + e]; }
      else      { s[j] = d[j] = e - NE; }
    }
  }
  #pragma unroll
  for(int j = 0; j < 8; j++)
    if(val[j]) pos[j] = atomicAdd(&g_fill[d[j]], 1);
  #pragma unroll
  for(int j = 0; j < 8; j++)
    if(val[j]) g_csrc[pos[j]] = s[j];
}

// ================= layer-0 LR GEMM (two 128-col passes, 96KB smem) =================
__global__ void __launch_bounds__(512, 2) k_mma_lr0(){
  extern __shared__ __align__(16) char smem[];
  const int tid = threadIdx.x, wid = tid >> 5, lane = tid & 31;
  const int bm = blockIdx.x * 128;
  const uint32_t sb = smem_u32(smem);
  for(int ch = tid; ch < 2048; ch += 512){
    int r = ch >> 4, c2 = (ch & 15) << 4;
    int grow = bm + r;
    uint32_t off = swA(r, c2);
    uint4 vh = make_uint4(0,0,0,0), vl = vh;
    if(grow < NN){
      vh = *(const uint4*)(g_ahi + grow*128 + (c2 >> 1));
      vl = *(const uint4*)(g_alo + grow*128 + (c2 >> 1));
    }
    *(uint4*)(smem + off)          = vh;
    *(uint4*)(smem + SM_ALO + off) = vl;
  }
  fill_B128(smem, tid, g_wh, 256, 0);         // Wl half
  __syncthreads();
  float acc[2][4][4];
  ZERO_ACC(acc);
  mma_compute128(sb, acc, wid, lane);
  __syncthreads();                            // B reads complete
  ep128<0>(acc, bm, wid, lane);               // overlap: epilogue stores ...
  fill_B128(smem, tid, g_wh, 256, 128);       // ... with Wr-half B fill
  __syncthreads();
  ZERO_ACC(acc);
  mma_compute128(sb, acc, wid, lane);
  ep128<1>(acc, bm, wid, lane);
}

// ================= fused skip-GEMM (+ next-layer LR GEMM, or final FC) =================
template<bool DO_LR>
__global__ void __launch_bounds__(512, 2) k_fused(const float* __restrict__ bias, int next_layer,
                                                  const float* __restrict__ fw,
                                                  const float* __restrict__ fb,
                                                  float* __restrict__ out){
  extern __shared__ __align__(16) char smem[];
  const int tid = threadIdx.x, wid = tid >> 5, lane = tid & 31;
  const int bm = blockIdx.x * 128;
  const uint32_t sb = smem_u32(smem);

  // ---- prologue: A = fp16split(normelu(h)), B = skW ----
  for(int ch = tid; ch < 2048; ch += 512){
    int r = ch >> 4, c2 = (ch & 15) << 4;
    int grow = bm + r;
    uint32_t off = swA(r, c2);
    int c = c2 >> 1;
    __half2 hh[4], ll[4];
    if(grow < NN){
      #pragma unroll
      for(int q = 0; q < 2; q++){
        float4 v  = *(const float4*)(g_h + grow*128 + c + q*4);
        float4 sc = *(const float4*)(g_scale + c + q*4);
        float4 sh = *(const float4*)(g_shift + c + q*4);
        float z0 = fmaf(v.x, sc.x, sh.x); z0 = z0 > 0.f ? z0 : (__expf(z0) - 1.f);
        float z1 = fmaf(v.y, sc.y, sh.y); z1 = z1 > 0.f ? z1 : (__expf(z1) - 1.f);
        float z2 = fmaf(v.z, sc.z, sh.z); z2 = z2 > 0.f ? z2 : (__expf(z2) - 1.f);
        float z3 = fmaf(v.w, sc.w, sh.w); z3 = z3 > 0.f ? z3 : (__expf(z3) - 1.f);
        hh[q*2].x   = __float2half_rn(z0); hh[q*2].y   = __float2half_rn(z1);
        hh[q*2+1].x = __float2half_rn(z2); hh[q*2+1].y = __float2half_rn(z3);
        ll[q*2].x   = __float2half_rn(z0 - __half2float(hh[q*2].x));
        ll[q*2].y   = __float2half_rn(z1 - __half2float(hh[q*2].y));
        ll[q*2+1].x = __float2half_rn(z2 - __half2float(hh[q*2+1].x));
        ll[q*2+1].y = __float2half_rn(z3 - __half2float(hh[q*2+1].y));
      }
    } else {
      #pragma unroll
      for(int q = 0; q < 4; q++){ hh[q].x = hh[q].y = __float2half_rn(0.f); ll[q] = hh[q]; }
    }
    *(uint4*)(smem + off)          = *(uint4*)hh;
    *(uint4*)(smem + SM_ALO + off) = *(uint4*)ll;
  }
  fill_B128(smem, tid, g_wh + 4*32768, 128, 0);
  __syncthreads();

  // ---- skip GEMM ----
  {
    float acc[2][4][4];
    ZERO_ACC(acc);
    mma_compute128(sb, acc, wid, lane);
    __syncthreads();               // A/B reads complete

    const int warp_m = wid >> 2, warp_n = wid & 3;
    #pragma unroll
    for(int mt = 0; mt < 2; mt++){
      int rloc0 = warp_m*32 + mt*16 + (lane >> 2);
      #pragma unroll
      for(int nt = 0; nt < 4; nt++){
        int col = warp_n*32 + nt*8 + (lane & 3)*2;
        #pragma unroll
        for(int half = 0; half < 2; half++){
          int rloc = rloc0 + half*8;
          int grow = bm + rloc;
          float v0 = acc[mt][nt][half*2], v1 = acc[mt][nt][half*2+1];
          if(grow < NN){
            float2 old = *(const float2*)(g_x + grow*128 + col);
            v0 += bias[col]   + old.x;
            v1 += bias[col+1] + old.y;
            *(float2*)(g_x + grow*128 + col) = make_float2(v0, v1);
          } else { v0 = 0.f; v1 = 0.f; }
          if(DO_LR){
            __half2 h, l;
            h.x = __float2half_rn(v0); h.y = __float2half_rn(v1);
            l.x = __float2half_rn(v0 - __half2float(h.x));
            l.y = __float2half_rn(v1 - __half2float(h.y));
            uint32_t off = swA(rloc, col*2);
            *(__half2*)(smem + off)          = h;
            *(__half2*)(smem + SM_ALO + off) = l;
          }
        }
      }
    }
    if(DO_LR)
      fill_B128(smem, tid, g_wh + next_layer*32768, 256, 0);  // Wl half, overlapped
  }
  if(!DO_LR){
    // ---- fused final FC + g_cnt re-zero for next call ----
    __syncthreads();
    int row = bm + (tid >> 2);
    int part = tid & 3;
    int rowc = row < NN ? row : (NN - 1);
    const float4* xp = (const float4*)(g_x + rowc*128 + part*32);
    float s = 0.f;
    #pragma unroll
    for(int q = 0; q < 8; q++){
      float4 v = xp[q];
      float4 w = *(const float4*)(fw + part*32 + q*4);
      s += v.x*w.x + v.y*w.y + v.z*w.z + v.w*w.w;
    }
    s += __shfl_xor_sync(0xffffffffu, s, 1);
    s += __shfl_xor_sync(0xffffffffu, s, 2);
    if(part == 0 && row < NN) out[row] = s + fb[0];
    for(int i = blockIdx.x*512 + tid; i < NN; i += gridDim.x*512)
      g_cnt[i] = 0;
    return;
  }

  __syncthreads();                 // A rewrite + B(Wl) fill visible
  {
    float acc[2][4][4];
    ZERO_ACC(acc);
    mma_compute128(sb, acc, wid, lane);
    __syncthreads();               // B reads complete
    ep128<0>(acc, bm, wid, lane);  // overlap epilogue with Wr B fill
    fill_B128(smem, tid, g_wh + next_layer*32768, 256, 128);
  }
  __syncthreads();
  {
    float acc[2][4][4];
    ZERO_ACC(acc);
    mma_compute128(sb, acc, wid, lane);
    ep128<1>(acc, bm, wid, lane);
  }
}

// ================= GATv2 (proven round-10 form) + fused GraphNorm =================
__device__ __forceinline__ float lrelu(float v){ return v > 0.f ? v : 0.2f*v; }

__global__ void __launch_bounds__(256) k_gat(const float* __restrict__ att,
                                             const float* __restrict__ convb,
                                             const float* __restrict__ gnw,
                                             const float* __restrict__ gnb,
                                             const float* __restrict__ gnms){
  __shared__ float s_sum[8][128];
  __shared__ float s_sq [8][128];
  __shared__ int s_last;
  int tid = threadIdx.x, wid = tid >> 5, lane = tid & 31;
  int node = blockIdx.x*8 + wid;
  int c4 = lane * 4;
  float4 o = make_float4(0.f, 0.f, 0.f, 0.f);

  if(node < NN){
    const float4 xr4 = *(const float4*)(g_xr + node*128 + c4);
    const float4 at4 = *(const float4*)(att + c4);
    int pb = g_rowptr[node], pe = g_rowptr[node+1];

    float m = -3.4e38f, ds = 0.f;
    float a0 = 0.f, a1 = 0.f, a2 = 0.f, a3 = 0.f;

    if(pb < pe){
      int sA = g_csrc[pb];
      uint2 rawN = *(const uint2*)(g_xlh + sA*128 + c4);
      int sB = (pb+1 < pe) ? g_csrc[pb+1] : 0;
      for(int p = pb; p < pe; p++){
        uint2 raw = rawN;
        if(p+1 < pe){
          rawN = *(const uint2*)(g_xlh + sB*128 + c4);
          if(p+2 < pe) sB = g_csrc[p+2];
        }
        float2 f0 = __half22float2(*(__half2*)&raw.x);
        float2 f1 = __half22float2(*(__half2*)&raw.y);
        float t = lrelu(f0.x + xr4.x)*at4.x + lrelu(f0.y + xr4.y)*at4.y
                + lrelu(f1.x + xr4.z)*at4.z + lrelu(f1.y + xr4.w)*at4.w;
        t += __shfl_xor_sync(0xffffffffu, t, 4);
        t += __shfl_xor_sync(0xffffffffu, t, 2);
        t += __shfl_xor_sync(0xffffffffu, t, 1);
        if(t <= m){
          float a = __expf(t - m);
          ds += a;
          a0 = fmaf(a, f0.x, a0); a1 = fmaf(a, f0.y, a1);
          a2 = fmaf(a, f1.x, a2); a3 = fmaf(a, f1.y, a3);
        } else {
          float f = __expf(m - t);
          ds = fmaf(ds, f, 1.f);
          a0 = fmaf(a0, f, f0.x); a1 = fmaf(a1, f, f0.y);
          a2 = fmaf(a2, f, f1.x); a3 = fmaf(a3, f, f1.y);
          m = t;
        }
      }
    }
    float inv = 1.f / ds;
    const float4 bb = *(const float4*)(convb + c4);
    o.x = fmaf(a0, inv, bb.x); o.y = fmaf(a1, inv, bb.y);
    o.z = fmaf(a2, inv, bb.z); o.w = fmaf(a3, inv, bb.w);
    *(float4*)(g_h + node*128 + c4) = o;
  }

  s_sum[wid][c4]   = o.x;     s_sum[wid][c4+1] = o.y;
  s_sum[wid][c4+2] = o.z;     s_sum[wid][c4+3] = o.w;
  s_sq [wid][c4]   = o.x*o.x; s_sq [wid][c4+1] = o.y*o.y;
  s_sq [wid][c4+2] = o.z*o.z; s_sq [wid][c4+3] = o.w*o.w;
  __syncthreads();
  if(tid < 128){
    float s = 0.f, q = 0.f;
    #pragma unroll
    for(int w = 0; w < 8; w++){ s += s_sum[w][tid]; q += s_sq[w][tid]; }
    atomicAdd(&g_stats[tid], s);
    atomicAdd(&g_stats[128 + tid], q);
  }
  __threadfence();
  if(tid == 0){
    int v = atomicAdd(&g_ctr, 1);
    s_last = (v == (int)gridDim.x - 1);
  }
  __syncthreads();
  if(s_last){
    if(tid < 128){
      float sum = g_stats[tid], sq = g_stats[128 + tid];
      float mean = sum * (1.f/(float)NN);
      float mv = gnms[tid] * mean;
      float var = sq * (1.f/(float)NN) - 2.f*mv*mean + mv*mv;
      float sc = gnw[tid] * rsqrtf(var + EPSV);
      g_scale[tid] = sc;
      g_shift[tid] = gnb[tid] - mv*sc;
      g_stats[tid] = 0.f; g_stats[128 + tid] = 0.f;
    }
    if(tid == 0) g_ctr = 0;
  }
}

// ================= launcher =================
extern "C" void kernel_launch(void* const* d_in, const int* in_sizes, int n_in,
                              void* d_out, int out_size){
  const float* x     = (const float*)d_in[0];
  const int*   ei    = (const int*)  d_in[1];
  const float* Wl    = (const float*)d_in[2];
  const float* Wr    = (const float*)d_in[3];
  const float* att   = (const float*)d_in[4];
  const float* convb = (const float*)d_in[5];
  const float* gnw   = (const float*)d_in[6];
  const float* gnb   = (const float*)d_in[7];
  const float* gnms  = (const float*)d_in[8];
  const float* skW   = (const float*)d_in[9];
  const float* skb   = (const float*)d_in[10];
  const float* fcW   = (const float*)d_in[11];
  const float* fcb   = (const float*)d_in[12];
  float* out = (float*)d_out;

  static int cfg_done = 0;
  static cudaStream_t s2;
  static cudaEvent_t evFork, evJoin;
  if(!cfg_done){
    cudaFuncSetAttribute(k_mma_lr0,      cudaFuncAttributeMaxDynamicSharedMemorySize, SMEM_TOT);
    cudaFuncSetAttribute(k_fused<true>,  cudaFuncAttributeMaxDynamicSharedMemorySize, SMEM_TOT);
    cudaFuncSetAttribute(k_fused<false>, cudaFuncAttributeMaxDynamicSharedMemorySize, SMEM_TOT);
    cudaStreamCreateWithFlags(&s2, cudaStreamNonBlocking);
    cudaEventCreateWithFlags(&evFork, cudaEventDisableTiming);
    cudaEventCreateWithFlags(&evJoin, cudaEventDisableTiming);
    cfg_done = 1;
  }

  k_setup<<<(NN*32 + 255)/256, 256>>>(x, ei, Wl, Wr, skW);
  // fork: CSR chain on s2, overlapping with layer-0 GEMM on the main stream
  cudaEventRecord(evFork, 0);
  cudaStreamWaitEvent(s2, evFork, 0);
  k_blocksum<<<SCAN_B, 256, 0, s2>>>();
  k_rowptr  <<<SCAN_B, 256, 0, s2>>>();
  k_scatter <<<(NT/8 + 255)/256, 256, 0, s2>>>(ei);
  cudaEventRecord(evJoin, s2);

  const int MMA_GRID = (NN + 127)/128;       // 391
  const int GAT_GRID = (NN + 7)/8;           // 6250
  k_mma_lr0<<<MMA_GRID, 512, SMEM_TOT>>>();
  cudaStreamWaitEvent(0, evJoin, 0);         // join before first gat
  for(int l = 0; l < 4; l++){
    k_gat<<<GAT_GRID, 256>>>(att + l*HID, convb + l*HID,
                             gnw + l*HID, gnb + l*HID, gnms + l*HID);
    if(l < 3) k_fused<true> <<<MMA_GRID, 512, SMEM_TOT>>>(skb, l + 1, nullptr, nullptr, nullptr);
    else      k_fused<false><<<MMA_GRID, 512, SMEM_TOT>>>(skb, 0, fcW, fcb, out);
  }
}